// round 7
// baseline (speedup 1.0000x reference)
#include <cuda_runtime.h>

// Problem shape (fixed by setup_inputs)
#define BQ 4
#define TT 96
#define NN 512
#define ROW_LEN 514              // [beta_logit, gamma_logit, z_0..z_511]
#define EPSV 1e-8f
#define BPB 37                   // 148 = 4 * 37 -> 1 block per SM
#define GRID (BQ * BPB)

// Scratch: ping-pong I vector + per-(b,t) barrier counters. S,I,R live in regs.
__device__ float    g_I[2][BQ][NN];
__device__ unsigned g_arrive[BQ * TT];

__global__ void reset_kernel() { g_arrive[threadIdx.x] = 0u; }

// ---------------------------------------------------------------------------
// Warp-specialized persistent kernel. 148 blocks x 512 threads, 1 block/SM.
//   warps 0..13  : STREAMING — free-running softmax/sigmoid producer.
//                  load params(b,t,row) -> softmax -> store epi (plain STG,
//                  stays L2-resident) -> fence -> bump s_prog[w]. Never waits.
//   warps 14..15 : SCAN — per step: wait local progress + per-batch global
//                  barrier, read beta/gamma/c back from epi via __ldcg (L2
//                  hit), dot with I (held in registers), SIR update in lanes,
//                  write out_view/g_I, arrive. Chain hides under streaming.
// No block-wide __syncthreads in the main loop; scan warps sync via named
// barrier 1 (64 threads).
// ---------------------------------------------------------------------------
__global__ __launch_bounds__(512, 1)
void fused_kernel(const float* __restrict__ x0,
                  const float* __restrict__ params,
                  float* __restrict__ out_view,
                  float* __restrict__ epi) {
    const int blk      = blockIdx.x;
    const int b        = blk / BPB;
    const int jloc     = blk - b * BPB;
    const int rowStart = (jloc * NN) / BPB;
    const int rowEnd   = ((jloc + 1) * NN) / BPB;
    const int nLocal   = rowEnd - rowStart;        // 13 or 14
    const int tid  = threadIdx.x;
    const int lane = tid & 31;
    const int wid  = tid >> 5;

    __shared__ volatile int s_prog[14];
    if (tid < 14) s_prog[tid] = 0;
    __syncthreads();                               // only block-wide sync

    const size_t stepStride = (size_t)NN * ROW_LEN;

    if (wid < 14) {
        // ================= STREAMING ROLE =================
        const int row = rowStart + wid;
        if (row >= rowEnd) return;                 // idle warp in 13-row blocks
        const size_t base = ((size_t)(b * TT) * NN + row) * ROW_LEN;

        // prologue: t=0 in regs
        float2 z[8]; float bgz = 0.f;
        {
            const float* p = params + base;
            const float2* p2 = (const float2*)(p + 2);
#pragma unroll
            for (int k = 0; k < 8; k++) z[k] = __ldcs(p2 + lane + 32 * k);
            if (lane < 2) bgz = __ldcs(p + lane);
        }

        for (int t = 0; t < TT; t++) {
            // prefetch t+1 (in flight through softmax/stores of t)
            float2 zn[8]; float bgn = 0.f;
            if (t + 1 < TT) {
                const float* p = params + base + (size_t)(t + 1) * stepStride;
                const float2* p2 = (const float2*)(p + 2);
#pragma unroll
                for (int k = 0; k < 8; k++) zn[k] = __ldcs(p2 + lane + 32 * k);
                if (lane < 2) bgn = __ldcs(p + lane);
            }

            // softmax
            float mx = -3.4e38f;
#pragma unroll
            for (int k = 0; k < 8; k++) mx = fmaxf(mx, fmaxf(z[k].x, z[k].y));
#pragma unroll
            for (int off = 16; off; off >>= 1)
                mx = fmaxf(mx, __shfl_xor_sync(0xffffffffu, mx, off));
            float s = 0.f;
#pragma unroll
            for (int k = 0; k < 8; k++) {
                z[k].x = __expf(z[k].x - mx);
                z[k].y = __expf(z[k].y - mx);
                s += z[k].x + z[k].y;
            }
#pragma unroll
            for (int off = 16; off; off >>= 1)
                s += __shfl_xor_sync(0xffffffffu, s, off);
            const float inv = 1.0f / s;

            // store epi(t) with default policy (keep in L2 for the scan)
            float* o = epi + base + (size_t)t * stepStride;
            if (lane < 2) o[lane] = 1.0f / (1.0f + __expf(-bgz));
            float2* o2 = (float2*)(o + 2);
#pragma unroll
            for (int k = 0; k < 8; k++) {
                z[k].x *= inv; z[k].y *= inv;
                o2[lane + 32 * k] = z[k];
            }

            __threadfence();                       // publish epi(t) (release)
            if (lane == 0) s_prog[wid] = t + 1;

#pragma unroll
            for (int k = 0; k < 8; k++) z[k] = zn[k];
            bgz = bgn;
        }
    } else {
        // ================= SCAN ROLE (warps 14,15) =================
        const int sw = wid - 14;                   // 0 or 1
        const int r0 = sw * 7;                     // local row base
        const int nr = min(7, nLocal - r0);        // 7 / 6-7 rows

        // persistent SIR state: lane r holds row rowStart+r0+r
        float S = 0.f, I = 0.f, R = 0.f;
        if (lane < nr) {
            const float* xr = x0 + (size_t)(b * NN + rowStart + r0 + lane) * 3;
            S = xr[0]; I = xr[1]; R = xr[2];
        }

        for (int t = 0; t < TT; t++) {
            if (sw == 0) {
                // wait local producers: epi(b,t) rows of this block stored
                for (;;) {
                    int p = (lane < nLocal) ? s_prog[lane] : 0x7fffffff;
                    if (__all_sync(0xffffffffu, p >= t + 1)) break;
                }
                // wait global per-batch barrier for step t-1
                if (t > 0 && lane == 0) {
                    volatile unsigned* vf = g_arrive + (b * TT + t - 1);
                    while (*vf < BPB) { }
                }
                __threadfence();                   // acquire
            }
            asm volatile("bar.sync 1, 64;" ::: "memory");

            // load I(t-1): lane pattern matches c float2 layout
            float2 Iv[8];
            if (t == 0) {
#pragma unroll
                for (int k = 0; k < 8; k++) {
                    const int e = 2 * (lane + 32 * k);
                    Iv[k].x = x0[(b * NN + e) * 3 + 1];
                    Iv[k].y = x0[(b * NN + e + 1) * 3 + 1];
                }
            } else {
                const float2* Ij = (const float2*)&g_I[t & 1][b][0];
#pragma unroll
                for (int k = 0; k < 8; k++) Iv[k] = __ldcg(Ij + lane + 32 * k);
            }

            // per-row dot against just-produced c(t) (L2-hot __ldcg)
            float beta = 0.f, gamma = 0.f, infect = 0.f;
            for (int r = 0; r < nr; r++) {
                const int row = rowStart + r0 + r;
                const float* crow = epi + ((size_t)(b * TT + t) * NN + row) * ROW_LEN;
                const float2 bg2 = __ldcg((const float2*)crow);   // (beta,gamma)
                const float2* c2 = (const float2*)(crow + 2);
                float acc = 0.f;
#pragma unroll
                for (int k = 0; k < 8; k++) {
                    const float2 cv = __ldcg(c2 + lane + 32 * k);
                    acc = fmaf(cv.x, Iv[k].x, fmaf(cv.y, Iv[k].y, acc));
                }
#pragma unroll
                for (int off = 16; off; off >>= 1)
                    acc += __shfl_xor_sync(0xffffffffu, acc, off);
                if (lane == r) { infect = acc; beta = bg2.x; gamma = bg2.y; }
            }

            // SIR update, lanes 0..nr-1 in parallel
            if (lane < nr) {
                const float Np = fmaxf(S + I + R, EPSV);
                const float dS = -(beta * S * infect) / Np;
                const float dR = gamma * I;
                const float dI = -dS - dR;
                float St = fmaxf(S + dS, 0.f);
                float It = fmaxf(I + dI, 0.f);
                float Rt = fmaxf(R + dR, 0.f);
                const float sc = Np / fmaxf(St + It + Rt, EPSV);
                S = St * sc; I = It * sc; R = Rt * sc;

                const int row = rowStart + r0 + lane;
                g_I[(t + 1) & 1][b][row] = I;

                const size_t ov = ((size_t)(b * TT + t) * NN + row) * 3;
                __stcs(out_view + ov,     S);
                __stcs(out_view + ov + 1, I);
                __stcs(out_view + ov + 2, R);
            }

            asm volatile("bar.sync 1, 64;" ::: "memory");
            if (t < TT - 1 && sw == 0 && lane == 0) {
                __threadfence();                   // release g_I writes
                atomicAdd(&g_arrive[b * TT + t], 1u);
            }
        }
    }
}

// ---------------------------------------------------------------------------
// Launch
// ---------------------------------------------------------------------------
extern "C" void kernel_launch(void* const* d_in, const int* in_sizes, int n_in,
                              void* d_out, int out_size) {
    const float* x0;
    const float* params;
    if (in_sizes[0] == BQ * NN * 3) {
        x0     = (const float*)d_in[0];
        params = (const float*)d_in[1];
    } else {
        x0     = (const float*)d_in[1];
        params = (const float*)d_in[0];
    }

    float* out      = (float*)d_out;
    float* out_view = out;                              // (B,T,N,3)
    float* epi      = out + (size_t)BQ * TT * NN * 3;   // (B,T,N,514)

    reset_kernel<<<1, BQ * TT>>>();
    fused_kernel<<<GRID, 512>>>(x0, params, out_view, epi);
}

// round 8
// speedup vs baseline: 1.2804x; 1.2804x over previous
#include <cuda_runtime.h>

// Problem shape (fixed by setup_inputs)
#define BQ 4
#define TT 96
#define NN 512
#define ROW_LEN 514              // [beta_logit, gamma_logit, z_0..z_511]
#define EPSV 1e-8f
#define BPB 37                   // 148 = 4 * 37 -> 1 block per SM
#define GRID (BQ * BPB)

// Scratch: ping-pong I vector, per-(b,t) barrier counters, per-(blk,warp)
// streaming progress flags. S,I,R live in scan-warp registers.
__device__ float    g_I[2][BQ][NN];
__device__ unsigned g_arrive[BQ * TT];
__device__ unsigned g_prog[GRID][16];

__global__ void reset_kernel() {
    const int i = threadIdx.x;
    for (int k = i; k < BQ * TT; k += 512) g_arrive[k] = 0u;
    unsigned* p = &g_prog[0][0];
    for (int k = i; k < GRID * 16; k += 512) p[k] = 0u;
}

// --- scoped release/acquire primitives: flag ordering WITHOUT CCTL.IVALL ---
__device__ __forceinline__ unsigned ld_acq(const unsigned* p) {
    unsigned v;
    asm volatile("ld.acquire.gpu.global.u32 %0, [%1];" : "=r"(v) : "l"(p) : "memory");
    return v;
}
__device__ __forceinline__ void st_rel(unsigned* p, unsigned v) {
    asm volatile("st.release.gpu.global.u32 [%0], %1;" :: "l"(p), "r"(v) : "memory");
}
__device__ __forceinline__ void red_rel_add1(unsigned* p) {
    asm volatile("red.release.gpu.global.add.u32 [%0], 1;" :: "l"(p) : "memory");
}

// ---------------------------------------------------------------------------
// Warp-specialized persistent kernel. 148 blocks x 512 threads, 1 block/SM.
//   warps 0..13 : STREAMING — free-running producer. load params -> softmax
//                 -> weak STG epi -> st.release progress flag. Never waits,
//                 never fences.
//   warps 14,15 : SCAN — independent; each owns <=7 rows (state in lanes).
//                 Poll progress flags + per-batch barrier with ld.acquire,
//                 read c/I via __ldcg (L2-hot), dot+update, weak stores,
//                 red.release arrive (2 arrivals/block, threshold 74).
// No __syncthreads / bar.sync / __threadfence anywhere in the main loops.
// ---------------------------------------------------------------------------
__global__ __launch_bounds__(512, 1)
void fused_kernel(const float* __restrict__ x0,
                  const float* __restrict__ params,
                  float* __restrict__ out_view,
                  float* __restrict__ epi) {
    const int blk      = blockIdx.x;
    const int b        = blk / BPB;
    const int jloc     = blk - b * BPB;
    const int rowStart = (jloc * NN) / BPB;
    const int rowEnd   = ((jloc + 1) * NN) / BPB;
    const int nLocal   = rowEnd - rowStart;        // 13 or 14
    const int lane = threadIdx.x & 31;
    const int wid  = threadIdx.x >> 5;

    const size_t stepStride = (size_t)NN * ROW_LEN;

    if (wid < 14) {
        // ================= STREAMING ROLE =================
        const int row = rowStart + wid;
        if (row >= rowEnd) return;                 // idle warp in 13-row blocks
        const size_t base = ((size_t)(b * TT) * NN + row) * ROW_LEN;

        // prologue: params(t=0) in regs
        float2 z[8]; float bgz = 0.f;
        {
            const float* p = params + base;
            const float2* p2 = (const float2*)(p + 2);
#pragma unroll
            for (int k = 0; k < 8; k++) z[k] = __ldcs(p2 + lane + 32 * k);
            if (lane < 2) bgz = __ldcs(p + lane);
        }

        for (int t = 0; t < TT; t++) {
            // prefetch t+1 (in flight through softmax/stores of t)
            float2 zn[8]; float bgn = 0.f;
            if (t + 1 < TT) {
                const float* p = params + base + (size_t)(t + 1) * stepStride;
                const float2* p2 = (const float2*)(p + 2);
#pragma unroll
                for (int k = 0; k < 8; k++) zn[k] = __ldcs(p2 + lane + 32 * k);
                if (lane < 2) bgn = __ldcs(p + lane);
            }

            // softmax
            float mx = -3.4e38f;
#pragma unroll
            for (int k = 0; k < 8; k++) mx = fmaxf(mx, fmaxf(z[k].x, z[k].y));
#pragma unroll
            for (int off = 16; off; off >>= 1)
                mx = fmaxf(mx, __shfl_xor_sync(0xffffffffu, mx, off));
            float s = 0.f;
#pragma unroll
            for (int k = 0; k < 8; k++) {
                z[k].x = __expf(z[k].x - mx);
                z[k].y = __expf(z[k].y - mx);
                s += z[k].x + z[k].y;
            }
#pragma unroll
            for (int off = 16; off; off >>= 1)
                s += __shfl_xor_sync(0xffffffffu, s, off);
            const float inv = 1.0f / s;

            // weak stores, default policy (keep L2-resident for the scan)
            float* o = epi + base + (size_t)t * stepStride;
            if (lane < 2) o[lane] = 1.0f / (1.0f + __expf(-bgz));
            float2* o2 = (float2*)(o + 2);
#pragma unroll
            for (int k = 0; k < 8; k++) {
                z[k].x *= inv; z[k].y *= inv;
                o2[lane + 32 * k] = z[k];
            }

            // publish: release-store orders the epi stores, no L1 flush
            if (lane == 0) st_rel(&g_prog[blk][wid], (unsigned)(t + 1));

#pragma unroll
            for (int k = 0; k < 8; k++) z[k] = zn[k];
            bgz = bgn;
        }
    } else {
        // ================= SCAN ROLE (warps 14,15; independent) =================
        const int r0 = (wid - 14) * 7;             // local row base: 0 or 7
        const int nr = min(7, nLocal - r0);        // 7 / 6-7 rows

        // persistent SIR state: lane r holds row rowStart+r0+r
        float S = 0.f, I = 0.f, R = 0.f;
        if (lane < nr) {
            const float* xr = x0 + (size_t)(b * NN + rowStart + r0 + lane) * 3;
            S = xr[0]; I = xr[1]; R = xr[2];
        }

        for (int t = 0; t < TT; t++) {
            // wait for this block's producers to publish epi(t)
            for (;;) {
                unsigned p = (lane < nLocal) ? ld_acq(&g_prog[blk][lane])
                                             : 0xffffffffu;
                if (__all_sync(0xffffffffu, p >= (unsigned)(t + 1))) break;
            }
            // wait per-batch barrier for step t-1 (2 arrivals per block)
            if (t > 0) {
                if (lane == 0) {
                    while (ld_acq(&g_arrive[b * TT + t - 1]) < 2u * BPB) { }
                }
                __syncwarp();
            }

            // load I(t-1) to registers (lane pattern matches c float2 layout)
            float2 Iv[8];
            if (t == 0) {
#pragma unroll
                for (int k = 0; k < 8; k++) {
                    const int e = 2 * (lane + 32 * k);
                    Iv[k].x = x0[(b * NN + e) * 3 + 1];
                    Iv[k].y = x0[(b * NN + e + 1) * 3 + 1];
                }
            } else {
                const float2* Ij = (const float2*)&g_I[t & 1][b][0];
#pragma unroll
                for (int k = 0; k < 8; k++) Iv[k] = __ldcg(Ij + lane + 32 * k);
            }

            // per-row dot against just-produced c(t) (L2-hot, __ldcg)
            float beta = 0.f, gamma = 0.f, infect = 0.f;
#pragma unroll
            for (int r = 0; r < 7; r++) {
                if (r < nr) {
                    const float* crow = epi +
                        ((size_t)(b * TT + t) * NN + rowStart + r0 + r) * ROW_LEN;
                    const float2 bg2 = __ldcg((const float2*)crow); // (beta,gamma)
                    const float2* c2 = (const float2*)(crow + 2);
                    float acc = 0.f;
#pragma unroll
                    for (int k = 0; k < 8; k++) {
                        const float2 cv = __ldcg(c2 + lane + 32 * k);
                        acc = fmaf(cv.x, Iv[k].x, fmaf(cv.y, Iv[k].y, acc));
                    }
#pragma unroll
                    for (int off = 16; off; off >>= 1)
                        acc += __shfl_xor_sync(0xffffffffu, acc, off);
                    if (lane == r) { infect = acc; beta = bg2.x; gamma = bg2.y; }
                }
            }

            // SIR update, lanes 0..nr-1 in parallel
            if (lane < nr) {
                const float Np = fmaxf(S + I + R, EPSV);
                const float dS = -(beta * S * infect) / Np;
                const float dR = gamma * I;
                const float dI = -dS - dR;
                float St = fmaxf(S + dS, 0.f);
                float It = fmaxf(I + dI, 0.f);
                float Rt = fmaxf(R + dR, 0.f);
                const float sc = Np / fmaxf(St + It + Rt, EPSV);
                S = St * sc; I = It * sc; R = Rt * sc;

                const int row = rowStart + r0 + lane;
                g_I[(t + 1) & 1][b][row] = I;      // weak; ordered by red.release

                const size_t ov = ((size_t)(b * TT + t) * NN + row) * 3;
                __stcs(out_view + ov,     S);
                __stcs(out_view + ov + 1, I);
                __stcs(out_view + ov + 2, R);
            }

            // arrive: release-reduction orders this warp's g_I stores
            if (t < TT - 1 && lane == 0)
                red_rel_add1(&g_arrive[b * TT + t]);
        }
    }
}

// ---------------------------------------------------------------------------
// Launch
// ---------------------------------------------------------------------------
extern "C" void kernel_launch(void* const* d_in, const int* in_sizes, int n_in,
                              void* d_out, int out_size) {
    const float* x0;
    const float* params;
    if (in_sizes[0] == BQ * NN * 3) {
        x0     = (const float*)d_in[0];
        params = (const float*)d_in[1];
    } else {
        x0     = (const float*)d_in[1];
        params = (const float*)d_in[0];
    }

    float* out      = (float*)d_out;
    float* out_view = out;                              // (B,T,N,3)
    float* epi      = out + (size_t)BQ * TT * NN * 3;   // (B,T,N,514)

    reset_kernel<<<1, 512>>>();
    fused_kernel<<<GRID, 512>>>(x0, params, out_view, epi);
}

// round 9
// speedup vs baseline: 3.3928x; 2.6499x over previous
#include <cuda_runtime.h>

// Problem shape (fixed by setup_inputs)
#define BQ 4
#define TT 96
#define NN 512
#define ROW_LEN 514              // [beta_logit, gamma_logit, z_0..z_511]
#define EPSV 1e-8f
#define BPB 37                   // 148 = 4 * 37 -> 1 block per SM
#define GRID (BQ * BPB)
#define NSUB 4                   // arrival sub-counters per (b,t)
#define SUBPAD 64                // 64 u32 = 256B -> distinct L2 slices (bit7 transparent)

// Scratch: ping-pong I vector + spread per-(b,t) arrival counters.
// S,I,R live in each warp's registers; c flows softmax->dot in registers.
__device__ float    g_I[2][BQ][NN];
__device__ unsigned g_arrive[BQ][TT][NSUB][SUBPAD];

__global__ void reset_kernel() {
    unsigned* p = &g_arrive[0][0][0][0];
    const int total = BQ * TT * NSUB * SUBPAD;
    const int i = blockIdx.x * blockDim.x + threadIdx.x;
    if (i < total) p[i] = 0u;
}

// --- scoped release/acquire primitives (no fence -> no CCTL.IVALL L1 flush) ---
__device__ __forceinline__ unsigned ld_acq(const unsigned* p) {
    unsigned v;
    asm volatile("ld.acquire.gpu.global.u32 %0, [%1];" : "=r"(v) : "l"(p) : "memory");
    return v;
}
__device__ __forceinline__ void red_rel_add1(unsigned* p) {
    asm volatile("red.release.gpu.global.add.u32 [%0], 1;" :: "l"(p) : "memory");
}

// ---------------------------------------------------------------------------
// Warp-autonomous fused kernel. 148 blocks x 512 threads (1 block/SM), but the
// block plays NO role in synchronization: each warp owns one (b,row) lane for
// all 96 steps and runs its own loop:
//   issue prefetch params(t+1)            [in flight through everything below]
//   softmax(t) in regs -> store epi(t)    [c(t) stays in registers]
//   poll per-batch arrivals(t-1)          [ld.acquire, 4 spread sub-counters]
//   I(t-1) -> regs via __ldcg             [16 independent L2 loads]
//   dot(c regs, I regs) -> SIR update in lane0 persistent regs
//   store g_I / out_view ; red.release arrive(t)
// No __syncthreads / bar.sync / __threadfence anywhere in the loop.
// Backpressure is structural: a warp streams step t+1 only ~1 step ahead of
// its own scan, so c/I traffic is always L2-resident or register-resident.
// ---------------------------------------------------------------------------
__global__ __launch_bounds__(512, 1)
void fused_kernel(const float* __restrict__ x0,
                  const float* __restrict__ params,
                  float* __restrict__ out_view,
                  float* __restrict__ epi) {
    const int blk      = blockIdx.x;
    const int b        = blk / BPB;
    const int jloc     = blk - b * BPB;
    const int rowStart = (jloc * NN) / BPB;
    const int rowEnd   = ((jloc + 1) * NN) / BPB;
    const int lane = threadIdx.x & 31;
    const int wid  = threadIdx.x >> 5;

    const int row = rowStart + wid;
    if (row >= rowEnd) return;                     // idle warps exit; no bar use

    const int sub = row & (NSUB - 1);              // this warp's arrival counter

    // persistent SIR state (lane 0)
    float S = 0.f, I = 0.f, R = 0.f;
    if (lane == 0) {
        const float* xr = x0 + (size_t)(b * NN + row) * 3;
        S = xr[0]; I = xr[1]; R = xr[2];
    }

    const size_t stepStride = (size_t)NN * ROW_LEN;
    const size_t base = ((size_t)(b * TT) * NN + row) * ROW_LEN;

    // prologue: params(0) in regs
    float2 z[8]; float bgz = 0.f;
    {
        const float* p = params + base;
        const float2* p2 = (const float2*)(p + 2);
#pragma unroll
        for (int k = 0; k < 8; k++) z[k] = __ldcs(p2 + lane + 32 * k);
        if (lane < 2) bgz = __ldcs(p + lane);
    }

    for (int t = 0; t < TT; t++) {
        // ---- 1) prefetch params(t+1): in flight through softmax + poll ----
        float2 zn[8]; float bgn = 0.f;
        if (t + 1 < TT) {
            const float* p = params + base + (size_t)(t + 1) * stepStride;
            const float2* p2 = (const float2*)(p + 2);
#pragma unroll
            for (int k = 0; k < 8; k++) zn[k] = __ldcs(p2 + lane + 32 * k);
            if (lane < 2) bgn = __ldcs(p + lane);
        }

        // ---- 2) softmax(t): c stays in registers ----
        float mx = -3.4e38f;
#pragma unroll
        for (int k = 0; k < 8; k++) mx = fmaxf(mx, fmaxf(z[k].x, z[k].y));
#pragma unroll
        for (int off = 16; off; off >>= 1)
            mx = fmaxf(mx, __shfl_xor_sync(0xffffffffu, mx, off));
        float s = 0.f;
#pragma unroll
        for (int k = 0; k < 8; k++) {
            z[k].x = __expf(z[k].x - mx);
            z[k].y = __expf(z[k].y - mx);
            s += z[k].x + z[k].y;
        }
#pragma unroll
        for (int off = 16; off; off >>= 1)
            s += __shfl_xor_sync(0xffffffffu, s, off);
        const float inv = 1.0f / s;

        // store epi(t): streaming stores (never re-read; drain during poll)
        float* o = epi + base + (size_t)t * stepStride;
        float sb = 0.f;
        if (lane < 2) {
            sb = 1.0f / (1.0f + __expf(-bgz));
            __stcs(o + lane, sb);
        }
        float2* o2 = (float2*)(o + 2);
#pragma unroll
        for (int k = 0; k < 8; k++) {
            z[k].x *= inv; z[k].y *= inv;
            __stcs(o2 + lane + 32 * k, z[k]);
        }
        const float beta  = __shfl_sync(0xffffffffu, sb, 0);
        const float gamma = __shfl_sync(0xffffffffu, sb, 1);

        // ---- 3) wait: all 512 rows of batch b arrived for step t-1 ----
        if (t > 0) {
            for (;;) {
                unsigned c = 0xffffffffu;
                if (lane < NSUB) c = ld_acq(&g_arrive[b][t - 1][lane][0]);
                if (__all_sync(0xffffffffu, c >= (unsigned)(NN / NSUB))) break;
            }
        }

        // ---- 4) I(t-1) -> registers (pattern matches c float2 layout) ----
        float2 Iv[8];
        if (t == 0) {
#pragma unroll
            for (int k = 0; k < 8; k++) {
                const int e = 2 * (lane + 32 * k);
                Iv[k].x = x0[(b * NN + e) * 3 + 1];
                Iv[k].y = x0[(b * NN + e + 1) * 3 + 1];
            }
        } else {
            const float2* Ij = (const float2*)&g_I[t & 1][b][0];
#pragma unroll
            for (int k = 0; k < 8; k++) Iv[k] = __ldcg(Ij + lane + 32 * k);
        }

        // ---- 5) dot + SIR update ----
        float acc = 0.f;
#pragma unroll
        for (int k = 0; k < 8; k++)
            acc = fmaf(z[k].x, Iv[k].x, fmaf(z[k].y, Iv[k].y, acc));
#pragma unroll
        for (int off = 16; off; off >>= 1)
            acc += __shfl_xor_sync(0xffffffffu, acc, off);

        if (lane == 0) {
            const float Np = fmaxf(S + I + R, EPSV);
            const float dS = -(beta * S * acc) / Np;
            const float dR = gamma * I;
            const float dI = -dS - dR;
            float St = fmaxf(S + dS, 0.f);
            float It = fmaxf(I + dI, 0.f);
            float Rt = fmaxf(R + dR, 0.f);
            const float sc = Np / fmaxf(St + It + Rt, EPSV);
            S = St * sc; I = It * sc; R = Rt * sc;

            g_I[(t + 1) & 1][b][row] = I;          // ordered by red.release below

            const size_t ov = ((size_t)(b * TT + t) * NN + row) * 3;
            __stcs(out_view + ov,     S);
            __stcs(out_view + ov + 1, I);
            __stcs(out_view + ov + 2, R);
        }

        // ---- 6) arrive: release orders this warp's g_I store ----
        if (t < TT - 1 && lane == 0)
            red_rel_add1(&g_arrive[b][t][sub][0]);

        // rotate prefetch
#pragma unroll
        for (int k = 0; k < 8; k++) z[k] = zn[k];
        bgz = bgn;
    }
}

// ---------------------------------------------------------------------------
// Launch
// ---------------------------------------------------------------------------
extern "C" void kernel_launch(void* const* d_in, const int* in_sizes, int n_in,
                              void* d_out, int out_size) {
    const float* x0;
    const float* params;
    if (in_sizes[0] == BQ * NN * 3) {
        x0     = (const float*)d_in[0];
        params = (const float*)d_in[1];
    } else {
        x0     = (const float*)d_in[1];
        params = (const float*)d_in[0];
    }

    float* out      = (float*)d_out;
    float* out_view = out;                              // (B,T,N,3)
    float* epi      = out + (size_t)BQ * TT * NN * 3;   // (B,T,N,514)

    const int resetN = BQ * TT * NSUB * SUBPAD;
    reset_kernel<<<(resetN + 511) / 512, 512>>>();
    fused_kernel<<<GRID, 512>>>(x0, params, out_view, epi);
}